// round 5
// baseline (speedup 1.0000x reference)
#include <cuda_runtime.h>
#include <math.h>

// Problem shape (fixed): B=8, C=64, T=16, H=64, W=64, text_dim=768
#define NB 8
#define NC 64
#define NT 16
#define HW4 1024         // H*W/4 (float4 / longlong2 units per T-plane)
#define TD 768
#define NBC (NB*NC)      // 512
#define PF 4             // circular prefetch buffer depth (planes)

// Per-(b,c,t) sigmoid gates
__device__ float g_w[NBC * NT];   // 32 KB

// ---------------------------------------------------------------------------
// Kernel 1: gates only.  One block per (b,c); 16 groups of 16 threads.
// ---------------------------------------------------------------------------
__global__ __launch_bounds__(256) void gate_kernel(
    const float* __restrict__ E,    // (B, 768)
    const float* __restrict__ Wf,   // (C*T, 768)
    const float* __restrict__ bf)   // (C*T,)
{
    const int bc = blockIdx.x;
    const int b = bc >> 6;
    const int c = bc & 63;
    const int g = threadIdx.x >> 4;      // dot index 0..15
    const int l = threadIdx.x & 15;      // lane within group

    const int j = c * NT + g;
    const float4* e4 = (const float4*)(E  + (size_t)b * TD);
    const float4* w4 = (const float4*)(Wf + (size_t)j * TD);

    float s = 0.0f;
    #pragma unroll
    for (int d = l; d < TD / 4; d += 16) {       // 12 float4 per thread
        const float4 ev = e4[d];
        const float4 wv = w4[d];
        s = fmaf(ev.x, wv.x, s);
        s = fmaf(ev.y, wv.y, s);
        s = fmaf(ev.z, wv.z, s);
        s = fmaf(ev.w, wv.w, s);
    }
    #pragma unroll
    for (int o = 8; o; o >>= 1) s += __shfl_xor_sync(0xffffffffu, s, o);
    if (l == 0) {
        const float z = s + bf[j];
        g_w[bc * NT + g] = 1.0f / (1.0f + expf(-z));
    }
}

// ---------------------------------------------------------------------------
// Kernel 2: streaming modulation.  Grid (512, 8); 128 threads; float4 columns.
// y-resident (16 f32x2 pairs), x streamed through a PF-deep circular buffer
// whose WAR deps cap load batching -> continuous DRAM request flow.
// Target <=102 regs -> 5 blocks/SM (20 warps).
// ---------------------------------------------------------------------------
__global__ __launch_bounds__(128, 5) void mod_kernel(
    const longlong2* __restrict__ r,    // float4 planes as 2x f32x2
    longlong2* __restrict__ out)
{
    __shared__ float sw[NT];
    __shared__ float sD[NT][NT];
    __shared__ unsigned long long sM[NT][NT];   // duplicated (m,m) pairs, 2 KB

    const int bc = blockIdx.x;
    const int u = blockIdx.y * 128 + threadIdx.x;        // [0, 1024)
    const size_t base = (size_t)bc * (NT * HW4) + u;

    // Kick off the first PF plane loads (streaming)
    longlong2 x[PF];
    #pragma unroll
    for (int k = 0; k < PF; k++)
        x[k] = __ldcs(r + base + (size_t)k * HW4);

    // ---- prologue: build M = D^T diag(w) D under the in-flight loads ----
    if (threadIdx.x < NT) sw[threadIdx.x] = g_w[bc * NT + threadIdx.x];
    #pragma unroll
    for (int i = 0; i < 2; i++) {               // 128 threads -> 256 entries
        const int e = threadIdx.x + i * 128;
        const int k = e >> 4;
        const int t = e & 15;
        const float sc = (k == 0) ? 0.25f : 0.35355339059327373f; // sqrt(1/16), sqrt(2/16)
        sD[k][t] = cosf(3.14159265358979323846f * ((float)t + 0.5f) * (float)k / 16.0f) * sc;
    }
    __syncthreads();
    #pragma unroll
    for (int i = 0; i < 2; i++) {
        const int e = threadIdx.x + i * 128;
        const int to = e >> 4;
        const int ti = e & 15;
        float acc = 0.0f;
        #pragma unroll
        for (int kk = 0; kk < NT; kk++)
            acc = fmaf(sD[kk][to] * sw[kk], sD[kk][ti], acc);
        *(float2*)&sM[to][ti] = make_float2(acc, acc);   // duplicated pair
    }
    __syncthreads();

    // ---- mainloop: y[t] += M[t][k] * x[k], k-streamed through the ring ----
    unsigned long long yl[NT], yh[NT];
    #pragma unroll
    for (int t = 0; t < NT; t++) { yl[t] = 0ull; yh[t] = 0ull; }

    #pragma unroll
    for (int k = 0; k < NT; k++) {
        // consume slot, then refill it (WAR dep bounds hoisting to PF ahead)
        const unsigned long long xlo = (unsigned long long)x[k % PF].x;
        const unsigned long long xhi = (unsigned long long)x[k % PF].y;
        if (k + PF < NT)
            x[k % PF] = __ldcs(r + base + (size_t)(k + PF) * HW4);

        // M column k == row k (symmetric): 8 broadcast LDS.128
        #pragma unroll
        for (int t2 = 0; t2 < NT / 2; t2++) {
            const ulonglong2 m = *(const ulonglong2*)&sM[k][2 * t2];
            asm("fma.rn.f32x2 %0, %1, %2, %0;" : "+l"(yl[2*t2  ]) : "l"(m.x), "l"(xlo));
            asm("fma.rn.f32x2 %0, %1, %2, %0;" : "+l"(yh[2*t2  ]) : "l"(m.x), "l"(xhi));
            asm("fma.rn.f32x2 %0, %1, %2, %0;" : "+l"(yl[2*t2+1]) : "l"(m.y), "l"(xlo));
            asm("fma.rn.f32x2 %0, %1, %2, %0;" : "+l"(yh[2*t2+1]) : "l"(m.y), "l"(xhi));
        }
    }

    // ---- epilogue: 16 streaming STG.128 ----
    #pragma unroll
    for (int t = 0; t < NT; t++) {
        longlong2 y;
        y.x = (long long)yl[t];
        y.y = (long long)yh[t];
        __stcs(out + base + (size_t)t * HW4, y);
    }
}

// ---------------------------------------------------------------------------
extern "C" void kernel_launch(void* const* d_in, const int* in_sizes, int n_in,
                              void* d_out, int out_size)
{
    const float* r  = (const float*)d_in[0];   // (8,64,16,64,64)
    const float* E  = (const float*)d_in[1];   // (8,768)
    const float* Wf = (const float*)d_in[2];   // (1024,768)
    const float* bf = (const float*)d_in[3];   // (1024,)
    float* out = (float*)d_out;

    gate_kernel<<<NBC, 256>>>(E, Wf, bf);

    dim3 grid(NBC, 8);
    mod_kernel<<<grid, 128>>>((const longlong2*)r, (longlong2*)out);
}

// round 6
// speedup vs baseline: 1.0880x; 1.0880x over previous
#include <cuda_runtime.h>
#include <math.h>

// Problem shape (fixed): B=8, C=64, T=16, H=64, W=64, text_dim=768
#define NB 8
#define NC 64
#define NT 16
#define HW4 1024         // H*W/4 (float4 / longlong2 units per T-plane)
#define TD 768
#define NBC (NB*NC)      // 512

// Per-(b,c,t) sigmoid gates
__device__ float g_w[NBC * NT];   // 32 KB

__device__ __forceinline__ unsigned long long pack2(float v) {
    float2 f = make_float2(v, v);
    return *reinterpret_cast<unsigned long long*>(&f);
}

// ---------------------------------------------------------------------------
// Kernel 1: gates.  One block per c (64 blocks); Wf rows stay in registers,
// loop over the 8 batch rows of E (smem).  Wf read exactly once (3 MB).
// ---------------------------------------------------------------------------
__global__ __launch_bounds__(256) void gate_kernel(
    const float* __restrict__ E,    // (B, 768)
    const float* __restrict__ Wf,   // (C*T, 768)
    const float* __restrict__ bf)   // (C*T,)
{
    __shared__ float4 sE[NB][TD / 4];   // 24 KB

    const int c = blockIdx.x;
    const int g = threadIdx.x >> 4;      // row-in-c 0..15
    const int l = threadIdx.x & 15;      // lane within group

    // stage all of E (8 x 768 floats = 1536 float4)
    for (int i = threadIdx.x; i < NB * (TD / 4); i += 256)
        ((float4*)sE)[i] = ((const float4*)E)[i];

    // this thread's slice of Wf row j: 12 float4, kept in registers
    const int j = c * NT + g;
    const float4* w4 = (const float4*)(Wf + (size_t)j * TD);
    float4 wr[12];
    #pragma unroll
    for (int i = 0; i < 12; i++) wr[i] = w4[l + 16 * i];
    const float bj = bf[j];
    __syncthreads();

    #pragma unroll
    for (int b = 0; b < NB; b++) {
        float s = 0.0f;
        #pragma unroll
        for (int i = 0; i < 12; i++) {
            const float4 ev = sE[b][l + 16 * i];
            s = fmaf(ev.x, wr[i].x, s);
            s = fmaf(ev.y, wr[i].y, s);
            s = fmaf(ev.z, wr[i].z, s);
            s = fmaf(ev.w, wr[i].w, s);
        }
        #pragma unroll
        for (int o = 8; o; o >>= 1) s += __shfl_xor_sync(0xffffffffu, s, o);
        if (l == 0) {
            const float z = s + bj;
            g_w[(b * NC + c) * NT + g] = 1.0f / (1.0f + expf(-z));
        }
    }
}

// ---------------------------------------------------------------------------
// Kernel 2: streaming modulation with even/odd folding.
// Grid (512, 4); 256 threads; float4 columns; R2 memory structure
// (front-batch 16 LDG.128, transient accumulators, streamed STG.128),
// but compute folded via D[k][15-t] = (-1)^k D[k][t]:
//   s=x[j]+x[15-j], d=x[j]-x[15-j];  u=E s, v=O d;  y[t]=u+v, y[15-t]=u-v.
// Halves both FFMA2 count (512->256+adds) and LDS.128 count (128->64).
// ---------------------------------------------------------------------------
__global__ __launch_bounds__(256, 2) void mod_kernel(
    const longlong2* __restrict__ r,    // float4 planes as 2x f32x2
    longlong2* __restrict__ out)
{
    __shared__ float sw[NT];
    __shared__ float sD[NT][NT];
    __shared__ unsigned long long sE[8][8];   // duplicated (m,m) pairs
    __shared__ unsigned long long sO[8][8];

    const int bc = blockIdx.x;
    const int u = blockIdx.y * 256 + threadIdx.x;        // [0, 1024)
    const size_t base = (size_t)bc * (NT * HW4) + u;

    // Front-batched streaming loads: 16 independent LDG.128 (MLP=16)
    longlong2 x[NT];
    #pragma unroll
    for (int k = 0; k < NT; k++)
        x[k] = __ldcs(r + base + (size_t)k * HW4);

    // ---- prologue (hidden under loads): build E,O from gates ----
    if (threadIdx.x < NT) sw[threadIdx.x] = g_w[bc * NT + threadIdx.x];
    {
        const int k = threadIdx.x >> 4;
        const int t = threadIdx.x & 15;
        const float sc = (k == 0) ? 0.25f : 0.35355339059327373f; // sqrt(1/16), sqrt(2/16)
        sD[k][t] = cosf(3.14159265358979323846f * ((float)t + 0.5f) * (float)k / 16.0f) * sc;
    }
    __syncthreads();
    if (threadIdx.x < 128) {
        const int t   = (threadIdx.x >> 3) & 7;
        const int jj  = threadIdx.x & 7;
        const int odd = threadIdx.x >> 6;    // 0 -> E, 1 -> O
        float acc = 0.0f;
        #pragma unroll
        for (int m = 0; m < 8; m++) {
            const int k = 2 * m + odd;
            acc = fmaf(sD[k][t] * sw[k], sD[k][jj], acc);
        }
        const unsigned long long p = pack2(acc);
        if (odd) sO[t][jj] = p; else sE[t][jj] = p;
    }
    __syncthreads();

    // ---- fold: s/d (x dies here) ----
    const unsigned long long NEG1 = pack2(-1.0f);
    unsigned long long sl[8], sh[8], dl[8], dh[8];
    #pragma unroll
    for (int j = 0; j < 8; j++) {
        const unsigned long long al = (unsigned long long)x[j].x;
        const unsigned long long ah = (unsigned long long)x[j].y;
        const unsigned long long bl = (unsigned long long)x[15 - j].x;
        const unsigned long long bh = (unsigned long long)x[15 - j].y;
        asm("add.rn.f32x2 %0, %1, %2;"     : "=l"(sl[j]) : "l"(al), "l"(bl));
        asm("add.rn.f32x2 %0, %1, %2;"     : "=l"(sh[j]) : "l"(ah), "l"(bh));
        asm("fma.rn.f32x2 %0, %1, %2, %3;" : "=l"(dl[j]) : "l"(NEG1), "l"(bl), "l"(al));
        asm("fma.rn.f32x2 %0, %1, %2, %3;" : "=l"(dh[j]) : "l"(NEG1), "l"(bh), "l"(ah));
    }

    // ---- 8 folded rows: u = E[t]·s, v = O[t]·d ----
    #pragma unroll
    for (int t = 0; t < 8; t++) {
        unsigned long long ul = 0ull, uh = 0ull, vl = 0ull, vh = 0ull;
        #pragma unroll
        for (int j2 = 0; j2 < 4; j2++) {
            const ulonglong2 e = *(const ulonglong2*)&sE[t][2 * j2];  // LDS.128
            const ulonglong2 o = *(const ulonglong2*)&sO[t][2 * j2];  // LDS.128
            asm("fma.rn.f32x2 %0, %1, %2, %0;" : "+l"(ul) : "l"(e.x), "l"(sl[2*j2  ]));
            asm("fma.rn.f32x2 %0, %1, %2, %0;" : "+l"(uh) : "l"(e.x), "l"(sh[2*j2  ]));
            asm("fma.rn.f32x2 %0, %1, %2, %0;" : "+l"(ul) : "l"(e.y), "l"(sl[2*j2+1]));
            asm("fma.rn.f32x2 %0, %1, %2, %0;" : "+l"(uh) : "l"(e.y), "l"(sh[2*j2+1]));
            asm("fma.rn.f32x2 %0, %1, %2, %0;" : "+l"(vl) : "l"(o.x), "l"(dl[2*j2  ]));
            asm("fma.rn.f32x2 %0, %1, %2, %0;" : "+l"(vh) : "l"(o.x), "l"(dh[2*j2  ]));
            asm("fma.rn.f32x2 %0, %1, %2, %0;" : "+l"(vl) : "l"(o.y), "l"(dl[2*j2+1]));
            asm("fma.rn.f32x2 %0, %1, %2, %0;" : "+l"(vh) : "l"(o.y), "l"(dh[2*j2+1]));
        }
        longlong2 ya, yb;
        unsigned long long w0, w1;
        asm("add.rn.f32x2 %0, %1, %2;" : "=l"(w0) : "l"(ul), "l"(vl));
        asm("add.rn.f32x2 %0, %1, %2;" : "=l"(w1) : "l"(uh), "l"(vh));
        ya.x = (long long)w0; ya.y = (long long)w1;
        asm("fma.rn.f32x2 %0, %1, %2, %3;" : "=l"(w0) : "l"(NEG1), "l"(vl), "l"(ul));
        asm("fma.rn.f32x2 %0, %1, %2, %3;" : "=l"(w1) : "l"(NEG1), "l"(vh), "l"(uh));
        yb.x = (long long)w0; yb.y = (long long)w1;
        __stcs(out + base + (size_t)t * HW4, ya);
        __stcs(out + base + (size_t)(15 - t) * HW4, yb);
    }
}

// ---------------------------------------------------------------------------
extern "C" void kernel_launch(void* const* d_in, const int* in_sizes, int n_in,
                              void* d_out, int out_size)
{
    const float* r  = (const float*)d_in[0];   // (8,64,16,64,64)
    const float* E  = (const float*)d_in[1];   // (8,768)
    const float* Wf = (const float*)d_in[2];   // (1024,768)
    const float* bf = (const float*)d_in[3];   // (1024,)
    float* out = (float*)d_out;

    gate_kernel<<<NC, 256>>>(E, Wf, bf);

    dim3 grid(NBC, 4);
    mod_kernel<<<grid, 256>>>((const longlong2*)r, (longlong2*)out);
}